// round 6
// baseline (speedup 1.0000x reference)
#include <cuda_runtime.h>

#define DD 128
#define MAXN 100000
#define MAXE 1600000
#define CHUNK 1024
#define MAXBLK ((MAXN + CHUNK - 1) / CHUNK)

// Scratch (static __device__ arrays: allocation rules forbid cudaMalloc)
__device__ float g_h[MAXN * DD];        // post-GEMM features
__device__ float g_x[MAXN * DD];        // activation ping buffer
__device__ int   g_deg[MAXN];
__device__ float g_dis[MAXN];
__device__ int   g_rowptr[MAXN + 1];
__device__ int   g_cursor[MAXN];
__device__ int   g_col[MAXE];
__device__ float g_wgt[MAXE];
__device__ int   g_blocksum[MAXBLK + 1];

// ---------------- preprocessing ----------------

__global__ void k_zero_deg(int n) {
    int i = blockIdx.x * blockDim.x + threadIdx.x;
    if (i < n) g_deg[i] = 0;
}

__global__ void k_count(const int* __restrict__ dst, int e) {
    int i = blockIdx.x * blockDim.x + threadIdx.x;
    if (i < e) atomicAdd(&g_deg[dst[i]], 1);
}

__global__ void k_dis(int n) {
    int i = blockIdx.x * blockDim.x + threadIdx.x;
    if (i < n) g_dis[i] = rsqrtf((float)(g_deg[i] + 1));  // +1 self-loop
}

// exclusive scan of g_deg -> g_rowptr, 3-kernel (chunk = 1024)
__global__ void k_scan1(int n) {
    __shared__ int warp_tot[8];
    int t = threadIdx.x;              // 256 threads, 4 elems each
    int lane = t & 31, w = t >> 5;
    int base = blockIdx.x * CHUNK + t * 4;
    int vals[4];
#pragma unroll
    for (int j = 0; j < 4; j++) vals[j] = (base + j < n) ? g_deg[base + j] : 0;
    int s = vals[0] + vals[1] + vals[2] + vals[3];
    int sc = s;  // inclusive warp scan over per-thread sums
#pragma unroll
    for (int o = 1; o < 32; o <<= 1) {
        int v = __shfl_up_sync(0xffffffffu, sc, o);
        if (lane >= o) sc += v;
    }
    if (lane == 31) warp_tot[w] = sc;
    __syncthreads();
    if (w == 0 && lane < 8) {
        int ws = warp_tot[lane];
#pragma unroll
        for (int o = 1; o < 8; o <<= 1) {
            int v = __shfl_up_sync(0xffu, ws, o);
            if (lane >= o) ws += v;
        }
        warp_tot[lane] = ws;  // inclusive
    }
    __syncthreads();
    int excl = sc - s + (w > 0 ? warp_tot[w - 1] : 0);
    int run = excl;
#pragma unroll
    for (int j = 0; j < 4; j++) {
        if (base + j < n) g_rowptr[base + j] = run;
        run += vals[j];
    }
    if (t == 0) g_blocksum[blockIdx.x] = warp_tot[7];  // chunk total
}

__global__ void k_scan2(int n, int nblk) {
    if (threadIdx.x == 0) {
        int acc = 0;
        for (int i = 0; i < nblk; i++) {
            int v = g_blocksum[i];
            g_blocksum[i] = acc;
            acc += v;
        }
        g_rowptr[n] = acc;
    }
}

__global__ void k_scan3(int n) {
    int i = blockIdx.x * blockDim.x + threadIdx.x;
    if (i < n) {
        int r = g_rowptr[i] + g_blocksum[i >> 10];
        g_rowptr[i] = r;
        g_cursor[i] = r;
    }
}

__global__ void k_fill(const int* __restrict__ src, const int* __restrict__ dst, int e) {
    int i = blockIdx.x * blockDim.x + threadIdx.x;
    if (i < e) {
        int s = src[i], d = dst[i];
        int p = atomicAdd(&g_cursor[d], 1);
        g_col[p] = s;
        g_wgt[p] = g_dis[s] * g_dis[d];
    }
}

// ---------------- per-layer compute ----------------

// h = x @ W  — 4 rows per warp; each W float4 load amortized over 4 rows.
__global__ void __launch_bounds__(256)
k_gemm(const float* __restrict__ xin, const float* __restrict__ W, int n) {
    int warp = (blockIdx.x * blockDim.x + threadIdx.x) >> 5;
    int lane = threadIdx.x & 31;
    int row0 = warp * 4;
    if (row0 >= n) return;
    int nr = n - row0; if (nr > 4) nr = 4;

    float4 xv[4], acc[4];
#pragma unroll
    for (int r = 0; r < 4; r++) {
        if (r < nr) xv[r] = ((const float4*)(xin + (size_t)(row0 + r) * DD))[lane];
        else        xv[r] = make_float4(0.f, 0.f, 0.f, 0.f);
        acc[r] = make_float4(0.f, 0.f, 0.f, 0.f);
    }
#pragma unroll
    for (int kk = 0; kk < 32; kk++) {
        float4 w0 = __ldg((const float4*)(W + (4 * kk + 0) * DD) + lane);
        float4 w1 = __ldg((const float4*)(W + (4 * kk + 1) * DD) + lane);
        float4 w2 = __ldg((const float4*)(W + (4 * kk + 2) * DD) + lane);
        float4 w3 = __ldg((const float4*)(W + (4 * kk + 3) * DD) + lane);
#pragma unroll
        for (int r = 0; r < 4; r++) {
            float a0 = __shfl_sync(0xffffffffu, xv[r].x, kk);
            float a1 = __shfl_sync(0xffffffffu, xv[r].y, kk);
            float a2 = __shfl_sync(0xffffffffu, xv[r].z, kk);
            float a3 = __shfl_sync(0xffffffffu, xv[r].w, kk);
            acc[r].x += a0 * w0.x + a1 * w1.x + a2 * w2.x + a3 * w3.x;
            acc[r].y += a0 * w0.y + a1 * w1.y + a2 * w2.y + a3 * w3.y;
            acc[r].z += a0 * w0.z + a1 * w1.z + a2 * w2.z + a3 * w3.z;
            acc[r].w += a0 * w0.w + a1 * w1.w + a2 * w2.w + a3 * w3.w;
        }
    }
#pragma unroll
    for (int r = 0; r < 4; r++)
        if (r < nr) ((float4*)(g_h + (size_t)(row0 + r) * DD))[lane] = acc[r];
}

// out[i] = relu( dis[i]^2*h[i] + sum_j wgt[j]*h[col[j]] + b )  — warp per node,
// gather loop unrolled 4x for MLP.
__global__ void __launch_bounds__(256)
k_agg(const float* __restrict__ bl, float* __restrict__ xout, int n) {
    int gw = (blockIdx.x * blockDim.x + threadIdx.x) >> 5;
    int lane = threadIdx.x & 31;
    if (gw >= n) return;
    float4 bv = __ldg((const float4*)bl + lane);   // hoisted: overlaps gather latency
    float di = g_dis[gw];
    float sw = di * di;
    float4 hv = ((const float4*)(g_h + (size_t)gw * DD))[lane];
    float4 acc = make_float4(sw * hv.x, sw * hv.y, sw * hv.z, sw * hv.w);
    int beg = g_rowptr[gw], end = g_rowptr[gw + 1];
    int j = beg;
    for (; j + 4 <= end; j += 4) {
        int c0 = __ldg(&g_col[j + 0]), c1 = __ldg(&g_col[j + 1]);
        int c2 = __ldg(&g_col[j + 2]), c3 = __ldg(&g_col[j + 3]);
        float w0 = __ldg(&g_wgt[j + 0]), w1 = __ldg(&g_wgt[j + 1]);
        float w2 = __ldg(&g_wgt[j + 2]), w3 = __ldg(&g_wgt[j + 3]);
        float4 v0 = __ldg((const float4*)(g_h + (size_t)c0 * DD) + lane);
        float4 v1 = __ldg((const float4*)(g_h + (size_t)c1 * DD) + lane);
        float4 v2 = __ldg((const float4*)(g_h + (size_t)c2 * DD) + lane);
        float4 v3 = __ldg((const float4*)(g_h + (size_t)c3 * DD) + lane);
        acc.x += w0 * v0.x + w1 * v1.x + w2 * v2.x + w3 * v3.x;
        acc.y += w0 * v0.y + w1 * v1.y + w2 * v2.y + w3 * v3.y;
        acc.z += w0 * v0.z + w1 * v1.z + w2 * v2.z + w3 * v3.z;
        acc.w += w0 * v0.w + w1 * v1.w + w2 * v2.w + w3 * v3.w;
    }
    for (; j < end; j++) {
        int c = __ldg(&g_col[j]);
        float w = __ldg(&g_wgt[j]);
        float4 v = __ldg((const float4*)(g_h + (size_t)c * DD) + lane);
        acc.x += w * v.x;
        acc.y += w * v.y;
        acc.z += w * v.z;
        acc.w += w * v.w;
    }
    acc.x = fmaxf(acc.x + bv.x, 0.f);
    acc.y = fmaxf(acc.y + bv.y, 0.f);
    acc.z = fmaxf(acc.z + bv.z, 0.f);
    acc.w = fmaxf(acc.w + bv.w, 0.f);
    ((float4*)(xout + (size_t)gw * DD))[lane] = acc;
}

// ---------------- launch ----------------

extern "C" void kernel_launch(void* const* d_in, const int* in_sizes, int n_in,
                              void* d_out, int out_size) {
    const float* x = (const float*)d_in[0];
    const int* ei  = (const int*)d_in[1];
    const float* W = (const float*)d_in[2];
    const float* b = (const float*)d_in[3];
    int n = in_sizes[0] / DD;
    int e = in_sizes[1] / 2;
    int L = in_sizes[2] / (DD * DD);
    const int* src = ei;
    const int* dst = ei + e;

    float* gx = nullptr;
    cudaGetSymbolAddress((void**)&gx, g_x);

    const int tb = 256;
    k_zero_deg<<<(n + tb - 1) / tb, tb>>>(n);
    k_count<<<(e + tb - 1) / tb, tb>>>(dst, e);
    k_dis<<<(n + tb - 1) / tb, tb>>>(n);
    int nblk = (n + CHUNK - 1) / CHUNK;
    k_scan1<<<nblk, 256>>>(n);
    k_scan2<<<1, 32>>>(n, nblk);
    k_scan3<<<(n + tb - 1) / tb, tb>>>(n);
    k_fill<<<(e + tb - 1) / tb, tb>>>(src, dst, e);

    int gemm_warps = (n + 3) / 4;                 // 4 rows per warp
    int gemm_blocks = (gemm_warps + 7) / 8;       // 8 warps per block
    int agg_blocks = (n + 7) / 8;                 // warp per node
    const float* xin = x;
    for (int l = 0; l < L; l++) {
        k_gemm<<<gemm_blocks, 256>>>(xin, W + (size_t)l * DD * DD, n);
        float* xout = (l == L - 1) ? (float*)d_out : gx;
        k_agg<<<agg_blocks, 256>>>(b + (size_t)l * DD, xout, n);
        xin = gx;
    }
}

// round 13
// speedup vs baseline: 1.1042x; 1.1042x over previous
#include <cuda_runtime.h>
#include <cuda_bf16.h>
#include <mma.h>

using namespace nvcuda;

#define DD 128
#define MAXN 100000
#define MAXN_PAD 100032   // next multiple of 64, for padded GEMM stores
#define MAXE 1600000
#define CHUNK 1024
#define MAXBLK ((MAXN + CHUNK - 1) / CHUNK)

#define GEMM_TM 64        // rows per block
#define SPAD 136          // smem row stride (elements), mult of 8, breaks conflicts
#define GEMM_SMEM_BYTES ((2 * GEMM_TM * SPAD + 2 * DD * SPAD) * 2)  // 104448

// Scratch (static __device__ arrays: allocation rules forbid cudaMalloc)
__device__ float g_h[MAXN_PAD * DD];    // post-GEMM features (padded rows for wmma stores)
__device__ float g_x[MAXN * DD];        // activation ping buffer
__device__ int   g_deg[MAXN];
__device__ float g_dis[MAXN];
__device__ int   g_rowptr[MAXN + 1];
__device__ int   g_cursor[MAXN];
__device__ int   g_col[MAXE];
__device__ float g_wgt[MAXE];
__device__ int   g_blocksum[MAXBLK + 1];

// ---------------- preprocessing ----------------

__global__ void k_zero_deg(int n) {
    int i = blockIdx.x * blockDim.x + threadIdx.x;
    if (i < n) g_deg[i] = 0;
}

__global__ void k_count(const int* __restrict__ dst, int e) {
    int i = blockIdx.x * blockDim.x + threadIdx.x;
    if (i < e) atomicAdd(&g_deg[dst[i]], 1);
}

__global__ void k_dis(int n) {
    int i = blockIdx.x * blockDim.x + threadIdx.x;
    if (i < n) g_dis[i] = rsqrtf((float)(g_deg[i] + 1));  // +1 self-loop
}

// exclusive scan of g_deg -> g_rowptr, 3-kernel (chunk = 1024)
__global__ void k_scan1(int n) {
    __shared__ int warp_tot[8];
    int t = threadIdx.x;              // 256 threads, 4 elems each
    int lane = t & 31, w = t >> 5;
    int base = blockIdx.x * CHUNK + t * 4;
    int vals[4];
#pragma unroll
    for (int j = 0; j < 4; j++) vals[j] = (base + j < n) ? g_deg[base + j] : 0;
    int s = vals[0] + vals[1] + vals[2] + vals[3];
    int sc = s;
#pragma unroll
    for (int o = 1; o < 32; o <<= 1) {
        int v = __shfl_up_sync(0xffffffffu, sc, o);
        if (lane >= o) sc += v;
    }
    if (lane == 31) warp_tot[w] = sc;
    __syncthreads();
    if (w == 0 && lane < 8) {
        int ws = warp_tot[lane];
#pragma unroll
        for (int o = 1; o < 8; o <<= 1) {
            int v = __shfl_up_sync(0xffu, ws, o);
            if (lane >= o) ws += v;
        }
        warp_tot[lane] = ws;
    }
    __syncthreads();
    int excl = sc - s + (w > 0 ? warp_tot[w - 1] : 0);
    int run = excl;
#pragma unroll
    for (int j = 0; j < 4; j++) {
        if (base + j < n) g_rowptr[base + j] = run;
        run += vals[j];
    }
    if (t == 0) g_blocksum[blockIdx.x] = warp_tot[7];
}

__global__ void k_scan2(int n, int nblk) {
    if (threadIdx.x == 0) {
        int acc = 0;
        for (int i = 0; i < nblk; i++) {
            int v = g_blocksum[i];
            g_blocksum[i] = acc;
            acc += v;
        }
        g_rowptr[n] = acc;
    }
}

__global__ void k_scan3(int n) {
    int i = blockIdx.x * blockDim.x + threadIdx.x;
    if (i < n) {
        int r = g_rowptr[i] + g_blocksum[i >> 10];
        g_rowptr[i] = r;
        g_cursor[i] = r;
    }
}

__global__ void k_fill(const int* __restrict__ src, const int* __restrict__ dst, int e) {
    int i = blockIdx.x * blockDim.x + threadIdx.x;
    if (i < e) {
        int s = src[i], d = dst[i];
        int p = atomicAdd(&g_cursor[d], 1);
        g_col[p] = s;
        g_wgt[p] = g_dis[s] * g_dis[d];
    }
}

// ---------------- GEMM: bf16 split-precision wmma ----------------
// h = x @ W computed as x_hi@W_hi + x_lo@W_hi + x_hi@W_lo with fp32 accum.
// hi+lo represents fp32 to ~2^-17; dropped lo*lo term ~2^-18 — total error
// orders of magnitude under the 1e-3 threshold.

__device__ __forceinline__ void split_bf16(float v, __nv_bfloat16& hi, __nv_bfloat16& lo) {
    hi = __float2bfloat16(v);
    lo = __float2bfloat16(v - __bfloat162float(hi));
}

__global__ void __launch_bounds__(256)
k_gemm_wmma(const float* __restrict__ xin, const float* __restrict__ W, int n) {
    extern __shared__ __nv_bfloat16 smem[];
    __nv_bfloat16* sA_hi = smem;                       // [GEMM_TM][SPAD]
    __nv_bfloat16* sA_lo = sA_hi + GEMM_TM * SPAD;
    __nv_bfloat16* sB_hi = sA_lo + GEMM_TM * SPAD;     // [DD][SPAD]
    __nv_bfloat16* sB_lo = sB_hi + DD * SPAD;

    int tid = threadIdx.x;
    int row0 = blockIdx.x * GEMM_TM;

    // stage x tile (zero-pad rows >= n)
    for (int idx = tid; idx < GEMM_TM * DD; idx += 256) {
        int r = idx >> 7, c = idx & 127;
        int row = row0 + r;
        float v = (row < n) ? xin[(size_t)row * DD + c] : 0.f;
        __nv_bfloat16 hi, lo;
        split_bf16(v, hi, lo);
        sA_hi[r * SPAD + c] = hi;
        sA_lo[r * SPAD + c] = lo;
    }
    // stage full W (128x128)
    for (int idx = tid; idx < DD * DD; idx += 256) {
        int r = idx >> 7, c = idx & 127;
        float v = W[idx];
        __nv_bfloat16 hi, lo;
        split_bf16(v, hi, lo);
        sB_hi[r * SPAD + c] = hi;
        sB_lo[r * SPAD + c] = lo;
    }
    __syncthreads();

    // 8 warps; warp w computes a 32x32 output region: 2x2 tiles of 16x16
    int wid = tid >> 5;
    int tr = (wid >> 2) * 32;   // 0 or 32
    int tc = (wid & 3) * 32;    // 0,32,64,96

    wmma::fragment<wmma::accumulator, 16, 16, 16, float> acc[2][2];
#pragma unroll
    for (int i = 0; i < 2; i++)
#pragma unroll
        for (int j = 0; j < 2; j++) wmma::fill_fragment(acc[i][j], 0.f);

#pragma unroll
    for (int k = 0; k < DD / 16; k++) {
        wmma::fragment<wmma::matrix_a, 16, 16, 16, __nv_bfloat16, wmma::row_major> a_hi[2], a_lo[2];
        wmma::fragment<wmma::matrix_b, 16, 16, 16, __nv_bfloat16, wmma::row_major> b_hi[2], b_lo[2];
#pragma unroll
        for (int i = 0; i < 2; i++) {
            const __nv_bfloat16* pa = sA_hi + (tr + i * 16) * SPAD + k * 16;
            wmma::load_matrix_sync(a_hi[i], pa, SPAD);
            wmma::load_matrix_sync(a_lo[i], pa + (sA_lo - sA_hi), SPAD);
        }
#pragma unroll
        for (int j = 0; j < 2; j++) {
            const __nv_bfloat16* pb = sB_hi + (k * 16) * SPAD + tc + j * 16;
            wmma::load_matrix_sync(b_hi[j], pb, SPAD);
            wmma::load_matrix_sync(b_lo[j], pb + (sB_lo - sB_hi), SPAD);
        }
#pragma unroll
        for (int i = 0; i < 2; i++)
#pragma unroll
            for (int j = 0; j < 2; j++) {
                wmma::mma_sync(acc[i][j], a_hi[i], b_hi[j], acc[i][j]);
                wmma::mma_sync(acc[i][j], a_lo[i], b_hi[j], acc[i][j]);
                wmma::mma_sync(acc[i][j], a_hi[i], b_lo[j], acc[i][j]);
            }
    }

    // store (g_h rows padded to MAXN_PAD — partial last block writes stay in-bounds)
#pragma unroll
    for (int i = 0; i < 2; i++)
#pragma unroll
        for (int j = 0; j < 2; j++) {
            float* pd = g_h + (size_t)(row0 + tr + i * 16) * DD + tc + j * 16;
            wmma::store_matrix_sync(pd, acc[i][j], DD, wmma::mem_row_major);
        }
}

// ---------------- aggregation (unchanged, validated) ----------------

__global__ void __launch_bounds__(256)
k_agg(const float* __restrict__ bl, float* __restrict__ xout, int n) {
    int gw = (blockIdx.x * blockDim.x + threadIdx.x) >> 5;
    int lane = threadIdx.x & 31;
    if (gw >= n) return;
    float4 bv = __ldg((const float4*)bl + lane);
    float di = g_dis[gw];
    float sw = di * di;
    float4 hv = ((const float4*)(g_h + (size_t)gw * DD))[lane];
    float4 acc = make_float4(sw * hv.x, sw * hv.y, sw * hv.z, sw * hv.w);
    int beg = g_rowptr[gw], end = g_rowptr[gw + 1];
    int j = beg;
    for (; j + 4 <= end; j += 4) {
        int c0 = __ldg(&g_col[j + 0]), c1 = __ldg(&g_col[j + 1]);
        int c2 = __ldg(&g_col[j + 2]), c3 = __ldg(&g_col[j + 3]);
        float w0 = __ldg(&g_wgt[j + 0]), w1 = __ldg(&g_wgt[j + 1]);
        float w2 = __ldg(&g_wgt[j + 2]), w3 = __ldg(&g_wgt[j + 3]);
        float4 v0 = __ldg((const float4*)(g_h + (size_t)c0 * DD) + lane);
        float4 v1 = __ldg((const float4*)(g_h + (size_t)c1 * DD) + lane);
        float4 v2 = __ldg((const float4*)(g_h + (size_t)c2 * DD) + lane);
        float4 v3 = __ldg((const float4*)(g_h + (size_t)c3 * DD) + lane);
        acc.x += w0 * v0.x + w1 * v1.x + w2 * v2.x + w3 * v3.x;
        acc.y += w0 * v0.y + w1 * v1.y + w2 * v2.y + w3 * v3.y;
        acc.z += w0 * v0.z + w1 * v1.z + w2 * v2.z + w3 * v3.z;
        acc.w += w0 * v0.w + w1 * v1.w + w2 * v2.w + w3 * v3.w;
    }
    for (; j < end; j++) {
        int c = __ldg(&g_col[j]);
        float w = __ldg(&g_wgt[j]);
        float4 v = __ldg((const float4*)(g_h + (size_t)c * DD) + lane);
        acc.x += w * v.x;
        acc.y += w * v.y;
        acc.z += w * v.z;
        acc.w += w * v.w;
    }
    acc.x = fmaxf(acc.x + bv.x, 0.f);
    acc.y = fmaxf(acc.y + bv.y, 0.f);
    acc.z = fmaxf(acc.z + bv.z, 0.f);
    acc.w = fmaxf(acc.w + bv.w, 0.f);
    ((float4*)(xout + (size_t)gw * DD))[lane] = acc;
}

// ---------------- launch ----------------

extern "C" void kernel_launch(void* const* d_in, const int* in_sizes, int n_in,
                              void* d_out, int out_size) {
    const float* x = (const float*)d_in[0];
    const int* ei  = (const int*)d_in[1];
    const float* W = (const float*)d_in[2];
    const float* b = (const float*)d_in[3];
    int n = in_sizes[0] / DD;
    int e = in_sizes[1] / 2;
    int L = in_sizes[2] / (DD * DD);
    const int* src = ei;
    const int* dst = ei + e;

    float* gx = nullptr;
    cudaGetSymbolAddress((void**)&gx, g_x);

    cudaFuncSetAttribute(k_gemm_wmma, cudaFuncAttributeMaxDynamicSharedMemorySize,
                         GEMM_SMEM_BYTES);

    const int tb = 256;
    k_zero_deg<<<(n + tb - 1) / tb, tb>>>(n);
    k_count<<<(e + tb - 1) / tb, tb>>>(dst, e);
    k_dis<<<(n + tb - 1) / tb, tb>>>(n);
    int nblk = (n + CHUNK - 1) / CHUNK;
    k_scan1<<<nblk, 256>>>(n);
    k_scan2<<<1, 32>>>(n, nblk);
    k_scan3<<<(n + tb - 1) / tb, tb>>>(n);
    k_fill<<<(e + tb - 1) / tb, tb>>>(src, dst, e);

    int gemm_blocks = (n + GEMM_TM - 1) / GEMM_TM;
    int agg_blocks = (n + 7) / 8;                 // warp per node
    const float* xin = x;
    for (int l = 0; l < L; l++) {
        k_gemm_wmma<<<gemm_blocks, 256, GEMM_SMEM_BYTES>>>(xin, W + (size_t)l * DD * DD, n);
        float* xout = (l == L - 1) ? (float*)d_out : gx;
        k_agg<<<agg_blocks, 256>>>(b + (size_t)l * DD, xout, n);
        xin = gx;
    }
}

// round 15
// speedup vs baseline: 1.1802x; 1.0688x over previous
#include <cuda_runtime.h>
#include <cuda_bf16.h>
#include <mma.h>

using namespace nvcuda;

#define DD 128
#define MAXN 100000
#define MAXN_PAD 100032   // next multiple of 64, for padded GEMM stores
#define MAXE 1600000
#define CHUNK 1024
#define MAXBLK ((MAXN + CHUNK - 1) / CHUNK)

#define GEMM_TM 64        // rows per block
#define SPAD 136          // smem row stride (elements), mult of 8, breaks conflicts
#define GEMM_SMEM_BYTES ((2 * GEMM_TM * SPAD + 2 * DD * SPAD) * 2)  // 104448

// Scratch (static __device__ arrays: allocation rules forbid cudaMalloc)
__device__ float g_h[MAXN_PAD * DD];    // post-GEMM features (padded rows for wmma stores)
__device__ float g_x[MAXN * DD];        // activation ping buffer
__device__ int   g_deg[MAXN];
__device__ float g_dis[MAXN];
__device__ int   g_rowptr[MAXN + 1];
__device__ int   g_cursor[MAXN];
__device__ int   g_col[MAXE];
__device__ float g_wgt[MAXE];
__device__ int   g_blocksum[MAXBLK + 1];

// ---------------- preprocessing ----------------

__global__ void k_zero_deg(int n) {
    int i = blockIdx.x * blockDim.x + threadIdx.x;
    if (i < n) g_deg[i] = 0;
}

__global__ void k_count(const int* __restrict__ dst, int e) {
    int i = blockIdx.x * blockDim.x + threadIdx.x;
    if (i < e) atomicAdd(&g_deg[dst[i]], 1);
}

__global__ void k_dis(int n) {
    int i = blockIdx.x * blockDim.x + threadIdx.x;
    if (i < n) g_dis[i] = rsqrtf((float)(g_deg[i] + 1));  // +1 self-loop
}

// exclusive scan of g_deg -> g_rowptr, 3-kernel (chunk = 1024)
__global__ void k_scan1(int n) {
    __shared__ int warp_tot[8];
    int t = threadIdx.x;              // 256 threads, 4 elems each
    int lane = t & 31, w = t >> 5;
    int base = blockIdx.x * CHUNK + t * 4;
    int vals[4];
#pragma unroll
    for (int j = 0; j < 4; j++) vals[j] = (base + j < n) ? g_deg[base + j] : 0;
    int s = vals[0] + vals[1] + vals[2] + vals[3];
    int sc = s;
#pragma unroll
    for (int o = 1; o < 32; o <<= 1) {
        int v = __shfl_up_sync(0xffffffffu, sc, o);
        if (lane >= o) sc += v;
    }
    if (lane == 31) warp_tot[w] = sc;
    __syncthreads();
    if (w == 0 && lane < 8) {
        int ws = warp_tot[lane];
#pragma unroll
        for (int o = 1; o < 8; o <<= 1) {
            int v = __shfl_up_sync(0xffu, ws, o);
            if (lane >= o) ws += v;
        }
        warp_tot[lane] = ws;
    }
    __syncthreads();
    int excl = sc - s + (w > 0 ? warp_tot[w - 1] : 0);
    int run = excl;
#pragma unroll
    for (int j = 0; j < 4; j++) {
        if (base + j < n) g_rowptr[base + j] = run;
        run += vals[j];
    }
    if (t == 0) g_blocksum[blockIdx.x] = warp_tot[7];
}

__global__ void k_scan2(int n, int nblk) {
    if (threadIdx.x == 0) {
        int acc = 0;
        for (int i = 0; i < nblk; i++) {
            int v = g_blocksum[i];
            g_blocksum[i] = acc;
            acc += v;
        }
        g_rowptr[n] = acc;
    }
}

__global__ void k_scan3(int n) {
    int i = blockIdx.x * blockDim.x + threadIdx.x;
    if (i < n) {
        int r = g_rowptr[i] + g_blocksum[i >> 10];
        g_rowptr[i] = r;
        g_cursor[i] = r;
    }
}

__global__ void k_fill(const int* __restrict__ src, const int* __restrict__ dst, int e) {
    int i = blockIdx.x * blockDim.x + threadIdx.x;
    if (i < e) {
        int s = src[i], d = dst[i];
        int p = atomicAdd(&g_cursor[d], 1);
        g_col[p] = s;
        g_wgt[p] = g_dis[s] * g_dis[d];
    }
}

// ---------------- GEMM: bf16 split-precision wmma (validated R13) ----------------

__device__ __forceinline__ void split_bf16(float v, __nv_bfloat16& hi, __nv_bfloat16& lo) {
    hi = __float2bfloat16(v);
    lo = __float2bfloat16(v - __bfloat162float(hi));
}

__global__ void __launch_bounds__(256)
k_gemm_wmma(const float* __restrict__ xin, const float* __restrict__ W, int n) {
    extern __shared__ __nv_bfloat16 smem[];
    __nv_bfloat16* sA_hi = smem;                       // [GEMM_TM][SPAD]
    __nv_bfloat16* sA_lo = sA_hi + GEMM_TM * SPAD;
    __nv_bfloat16* sB_hi = sA_lo + GEMM_TM * SPAD;     // [DD][SPAD]
    __nv_bfloat16* sB_lo = sB_hi + DD * SPAD;

    int tid = threadIdx.x;
    int row0 = blockIdx.x * GEMM_TM;

    for (int idx = tid; idx < GEMM_TM * DD; idx += 256) {
        int r = idx >> 7, c = idx & 127;
        int row = row0 + r;
        float v = (row < n) ? xin[(size_t)row * DD + c] : 0.f;
        __nv_bfloat16 hi, lo;
        split_bf16(v, hi, lo);
        sA_hi[r * SPAD + c] = hi;
        sA_lo[r * SPAD + c] = lo;
    }
    for (int idx = tid; idx < DD * DD; idx += 256) {
        int r = idx >> 7, c = idx & 127;
        float v = W[idx];
        __nv_bfloat16 hi, lo;
        split_bf16(v, hi, lo);
        sB_hi[r * SPAD + c] = hi;
        sB_lo[r * SPAD + c] = lo;
    }
    __syncthreads();

    int wid = tid >> 5;
    int tr = (wid >> 2) * 32;
    int tc = (wid & 3) * 32;

    wmma::fragment<wmma::accumulator, 16, 16, 16, float> acc[2][2];
#pragma unroll
    for (int i = 0; i < 2; i++)
#pragma unroll
        for (int j = 0; j < 2; j++) wmma::fill_fragment(acc[i][j], 0.f);

#pragma unroll
    for (int k = 0; k < DD / 16; k++) {
        wmma::fragment<wmma::matrix_a, 16, 16, 16, __nv_bfloat16, wmma::row_major> a_hi[2], a_lo[2];
        wmma::fragment<wmma::matrix_b, 16, 16, 16, __nv_bfloat16, wmma::row_major> b_hi[2], b_lo[2];
#pragma unroll
        for (int i = 0; i < 2; i++) {
            const __nv_bfloat16* pa = sA_hi + (tr + i * 16) * SPAD + k * 16;
            wmma::load_matrix_sync(a_hi[i], pa, SPAD);
            wmma::load_matrix_sync(a_lo[i], pa + (sA_lo - sA_hi), SPAD);
        }
#pragma unroll
        for (int j = 0; j < 2; j++) {
            const __nv_bfloat16* pb = sB_hi + (k * 16) * SPAD + tc + j * 16;
            wmma::load_matrix_sync(b_hi[j], pb, SPAD);
            wmma::load_matrix_sync(b_lo[j], pb + (sB_lo - sB_hi), SPAD);
        }
#pragma unroll
        for (int i = 0; i < 2; i++)
#pragma unroll
            for (int j = 0; j < 2; j++) {
                wmma::mma_sync(acc[i][j], a_hi[i], b_hi[j], acc[i][j]);
                wmma::mma_sync(acc[i][j], a_lo[i], b_hi[j], acc[i][j]);
                wmma::mma_sync(acc[i][j], a_hi[i], b_lo[j], acc[i][j]);
            }
    }

#pragma unroll
    for (int i = 0; i < 2; i++)
#pragma unroll
        for (int j = 0; j < 2; j++) {
            float* pd = g_h + (size_t)(row0 + tr + i * 16) * DD + tc + j * 16;
            wmma::store_matrix_sync(pd, acc[i][j], DD, wmma::mem_row_major);
        }
}

// ---------------- aggregation: 8-wide gather pipeline (MLP 8) ----------------

__global__ void __launch_bounds__(256)
k_agg(const float* __restrict__ bl, float* __restrict__ xout, int n) {
    int gw = (blockIdx.x * blockDim.x + threadIdx.x) >> 5;
    int lane = threadIdx.x & 31;
    if (gw >= n) return;
    float4 bv = __ldg((const float4*)bl + lane);
    float di = g_dis[gw];
    float sw = di * di;
    float4 hv = ((const float4*)(g_h + (size_t)gw * DD))[lane];
    float4 acc = make_float4(sw * hv.x, sw * hv.y, sw * hv.z, sw * hv.w);
    int beg = g_rowptr[gw], end = g_rowptr[gw + 1];
    int j = beg;
    // 8-wide: 8 independent gathers in flight per round
    for (; j + 8 <= end; j += 8) {
        int   c[8];
        float w[8];
#pragma unroll
        for (int u = 0; u < 8; u++) { c[u] = __ldg(&g_col[j + u]); w[u] = __ldg(&g_wgt[j + u]); }
        float4 v[8];
#pragma unroll
        for (int u = 0; u < 8; u++)
            v[u] = __ldg((const float4*)(g_h + (size_t)c[u] * DD) + lane);
#pragma unroll
        for (int u = 0; u < 8; u++) {
            acc.x += w[u] * v[u].x;
            acc.y += w[u] * v[u].y;
            acc.z += w[u] * v[u].z;
            acc.w += w[u] * v[u].w;
        }
    }
    // 4-wide tail
    for (; j + 4 <= end; j += 4) {
        int c0 = __ldg(&g_col[j + 0]), c1 = __ldg(&g_col[j + 1]);
        int c2 = __ldg(&g_col[j + 2]), c3 = __ldg(&g_col[j + 3]);
        float w0 = __ldg(&g_wgt[j + 0]), w1 = __ldg(&g_wgt[j + 1]);
        float w2 = __ldg(&g_wgt[j + 2]), w3 = __ldg(&g_wgt[j + 3]);
        float4 v0 = __ldg((const float4*)(g_h + (size_t)c0 * DD) + lane);
        float4 v1 = __ldg((const float4*)(g_h + (size_t)c1 * DD) + lane);
        float4 v2 = __ldg((const float4*)(g_h + (size_t)c2 * DD) + lane);
        float4 v3 = __ldg((const float4*)(g_h + (size_t)c3 * DD) + lane);
        acc.x += w0 * v0.x + w1 * v1.x + w2 * v2.x + w3 * v3.x;
        acc.y += w0 * v0.y + w1 * v1.y + w2 * v2.y + w3 * v3.y;
        acc.z += w0 * v0.z + w1 * v1.z + w2 * v2.z + w3 * v3.z;
        acc.w += w0 * v0.w + w1 * v1.w + w2 * v2.w + w3 * v3.w;
    }
    for (; j < end; j++) {
        int c = __ldg(&g_col[j]);
        float w = __ldg(&g_wgt[j]);
        float4 v = __ldg((const float4*)(g_h + (size_t)c * DD) + lane);
        acc.x += w * v.x;
        acc.y += w * v.y;
        acc.z += w * v.z;
        acc.w += w * v.w;
    }
    acc.x = fmaxf(acc.x + bv.x, 0.f);
    acc.y = fmaxf(acc.y + bv.y, 0.f);
    acc.z = fmaxf(acc.z + bv.z, 0.f);
    acc.w = fmaxf(acc.w + bv.w, 0.f);
    ((float4*)(xout + (size_t)gw * DD))[lane] = acc;
}

// ---------------- launch ----------------

extern "C" void kernel_launch(void* const* d_in, const int* in_sizes, int n_in,
                              void* d_out, int out_size) {
    const float* x = (const float*)d_in[0];
    const int* ei  = (const int*)d_in[1];
    const float* W = (const float*)d_in[2];
    const float* b = (const float*)d_in[3];
    int n = in_sizes[0] / DD;
    int e = in_sizes[1] / 2;
    int L = in_sizes[2] / (DD * DD);
    const int* src = ei;
    const int* dst = ei + e;

    float* gx = nullptr;
    cudaGetSymbolAddress((void**)&gx, g_x);

    cudaFuncSetAttribute(k_gemm_wmma, cudaFuncAttributeMaxDynamicSharedMemorySize,
                         GEMM_SMEM_BYTES);

    const int tb = 256;
    k_zero_deg<<<(n + tb - 1) / tb, tb>>>(n);
    k_count<<<(e + tb - 1) / tb, tb>>>(dst, e);
    k_dis<<<(n + tb - 1) / tb, tb>>>(n);
    int nblk = (n + CHUNK - 1) / CHUNK;
    k_scan1<<<nblk, 256>>>(n);
    k_scan2<<<1, 32>>>(n, nblk);
    k_scan3<<<(n + tb - 1) / tb, tb>>>(n);
    k_fill<<<(e + tb - 1) / tb, tb>>>(src, dst, e);

    int gemm_blocks = (n + GEMM_TM - 1) / GEMM_TM;
    int agg_blocks = (n + 7) / 8;                 // warp per node
    const float* xin = x;
    for (int l = 0; l < L; l++) {
        k_gemm_wmma<<<gemm_blocks, 256, GEMM_SMEM_BYTES>>>(xin, W + (size_t)l * DD * DD, n);
        float* xout = (l == L - 1) ? (float*)d_out : gx;
        k_agg<<<agg_blocks, 256>>>(b + (size_t)l * DD, xout, n);
        xin = gx;
    }
}